// round 11
// baseline (speedup 1.0000x reference)
#include <cuda_runtime.h>
#include <math.h>

// Problem constants
#define Bc 32
#define Sc 1024
#define Ec 256
#define Hc 256
#define NCTA 128      // 64 CTAs per direction, 4 hidden units each
#define TPB 256       // 8 warps
#define NPAR 8        // parity depth of the h/s exchange buffers

// Output section offsets (floats)
#define OUT_C 16777216UL          // S*B*2H
#define OUT_S 33554432UL          // 2 * S*B*2H

// SMEM layout (float offsets)
#define OFF_WA   0        // [16 cols][772]   z-projection weights (x|h|s stacked on k)
#define OFF_WB   12352    // [8 cols][516]    r-projection weights (x|h stacked on k)
#define OFF_BA   16480    // [16]
#define OFF_BB   16496    // [16]
#define OFF_SIN  16512    // [32 b][772]      x staging (cols 0:256 used)
#define OFF_PRED 41216    // [8 warps][520]   k-split partials
#define OFF_CLOC 45376    // [4 jj][32 b]     cell state (CTA-local, persistent)
#define OFF_SLOC 45504    // [8 c][32 b]      shared state (CTA-local, persistent)
#define OFF_HTMP 45760    // [4 jj][32 b]     h state (CTA-local, persistent)
#define OFF_MASKW 45888   // [8 warps][32]    per-warp mask copies
#define SMEM_FLOATS 46144
#define SMEM_BYTES (SMEM_FLOATS * 4)

// Exchange buffers, NPAR-deep by step parity. [par][dir][b][j]
__device__ float g_h[NPAR * 2 * Bc * Hc];
__device__ float g_s[NPAR * 2 * Bc * Hc];     // share idx only
// One monotone epoch flag per CTA, padded to 32B.
__device__ unsigned g_flags[NCTA * 8];

__global__ void init_kernel() {
    int tid = blockIdx.x * blockDim.x + threadIdx.x;
    int stride = gridDim.x * blockDim.x;
    for (int i = tid; i < NPAR * 2 * Bc * Hc; i += stride) { g_h[i] = 0.0f; g_s[i] = 0.0f; }
    for (int i = tid; i < NCTA * 8; i += stride) g_flags[i] = 0u;
}

__device__ __forceinline__ float sigf(float x) {
    return __fdividef(1.0f, 1.0f + __expf(-x));
}
__device__ __forceinline__ float tanhf_fast(float x) {
    return 1.0f - __fdividef(2.0f, __expf(2.0f * x) + 1.0f);
}

// Packed dual-fp32 FMA (sm_103a).
__device__ __forceinline__ void fma2(unsigned long long& d,
                                     const unsigned long long a,
                                     const unsigned long long b) {
    asm("fma.rn.f32x2 %0, %1, %2, %0;" : "+l"(d) : "l"(a), "l"(b));
}
__device__ __forceinline__ float pair_sum(unsigned long long v) {
    float lo = __uint_as_float((unsigned int)(v & 0xffffffffULL));
    float hi = __uint_as_float((unsigned int)(v >> 32));
    return lo + hi;
}

// cp.async helpers
__device__ __forceinline__ void cp16(const float* smem_ptr, const float* gptr) {
    unsigned sa = (unsigned)__cvta_generic_to_shared(smem_ptr);
    asm volatile("cp.async.cg.shared.global [%0], [%1], 16;" :: "r"(sa), "l"(gptr));
}
__device__ __forceinline__ void cp4(const float* smem_ptr, const float* gptr) {
    unsigned sa = (unsigned)__cvta_generic_to_shared(smem_ptr);
    asm volatile("cp.async.ca.shared.global [%0], [%1], 4;" :: "r"(sa), "l"(gptr));
}
#define CP_COMMIT asm volatile("cp.async.commit_group;")
#define CP_WAIT0  asm volatile("cp.async.wait_group 0;")

// Warp-local producer wait, low-contention version:
// only lanes 0-7 load (relaxed) the 8 producer flags; backoff via nanosleep
// after the first failed round; one acquire fence at the end.
__device__ __forceinline__ void wait_producers(int dir, int warp, int lane, unsigned e) {
    const unsigned* fp = &g_flags[(unsigned)(dir * 64 + warp * 8 + (lane & 7)) * 8];
    bool mine_ok = (lane >= 8);
    unsigned v;
    if (!mine_ok) {
        asm volatile("ld.relaxed.gpu.u32 %0, [%1];" : "=r"(v) : "l"(fp) : "memory");
        mine_ok = (v >= e);
    }
    while (!__all_sync(0xffffffffu, mine_ok)) {
        __nanosleep(32);
        if (lane < 8) {
            asm volatile("ld.relaxed.gpu.u32 %0, [%1];" : "=r"(v) : "l"(fp) : "memory");
            mine_ok = (v >= e);
        }
    }
    asm volatile("fence.acq_rel.gpu;" ::: "memory");
}

__device__ __forceinline__ void flag_release(int cta, unsigned e) {
    unsigned* f = &g_flags[(unsigned)cta * 8];
    asm volatile("st.release.gpu.u32 [%0], %1;" :: "l"(f), "r"(e) : "memory");
}

// Accumulate one 32-k segment with SMEM input (x): NC cols, stride WSTR.
template<int NC, int WSTR>
__device__ __forceinline__ void accum_part(const float* __restrict__ sm,
                                           unsigned long long* acc,
                                           int in_base, int w_base) {
    const float* inb = sm + in_base;
    const float* wb  = sm + w_base;
    #pragma unroll
    for (int kb = 0; kb < 8; ++kb) {
        ulonglong2 xv = *reinterpret_cast<const ulonglong2*>(inb + kb * 4);
        #pragma unroll
        for (int c = 0; c < NC; ++c) {
            ulonglong2 wv = *reinterpret_cast<const ulonglong2*>(wb + c * WSTR + kb * 4);
            fma2(acc[c], xv.x, wv.x);
            fma2(acc[c], xv.y, wv.y);
        }
    }
}

// Accumulate one 32-k segment with REGISTER input (s/h slices).
template<int NC, int WSTR>
__device__ __forceinline__ void accum_reg(const float* __restrict__ sm,
                                          unsigned long long* acc,
                                          const ulonglong2* __restrict__ xr,
                                          int w_base) {
    const float* wb = sm + w_base;
    #pragma unroll
    for (int kb = 0; kb < 8; ++kb) {
        #pragma unroll
        for (int c = 0; c < NC; ++c) {
            ulonglong2 wv = *reinterpret_cast<const ulonglong2*>(wb + c * WSTR + kb * 4);
            fma2(acc[c], xr[kb].x, wv.x);
            fma2(acc[c], xr[kb].y, wv.y);
        }
    }
}

__global__ void __launch_bounds__(TPB, 1) bislstm_kernel(
    const float* __restrict__ inputs, const float* __restrict__ mask,
    const float* __restrict__ Wx,   const float* __restrict__ Wh,
    const float* __restrict__ Ws,   const float* __restrict__ bz,
    const float* __restrict__ Wrx,  const float* __restrict__ Wrh,
    const float* __restrict__ br,
    const float* __restrict__ Wx_r, const float* __restrict__ Wh_r,
    const float* __restrict__ Ws_r, const float* __restrict__ bz_r,
    const float* __restrict__ Wrx_r,const float* __restrict__ Wrh_r,
    const float* __restrict__ br_r,
    const int* __restrict__ idx_ptr, float* __restrict__ out)
{
    extern __shared__ float sm[];
    const int tid  = threadIdx.x;
    const int warp = tid >> 5;
    const int lane = tid & 31;
    const int cta  = blockIdx.x;
    const int dir  = cta >> 6;           // 0 = fwd, 1 = rev
    const int cid  = cta & 63;
    const int jbase = cid * 4;           // this CTA's 4 hidden units
    const int idxv = *idx_ptr;
    const int w32 = warp * 32;           // warp's k-offset inside each 256-segment

    const float* pWx  = dir ? Wx_r  : Wx;
    const float* pWh  = dir ? Wh_r  : Wh;
    const float* pWs  = dir ? Ws_r  : Ws;
    const float* pB   = dir ? bz_r  : bz;
    const float* pWrx = dir ? Wrx_r : Wrx;
    const float* pWrh = dir ? Wrh_r : Wrh;
    const float* pBr  = dir ? br_r  : br;

    // ---- Load weight slices into SMEM (once) ----
    for (int i = tid; i < 16 * 768; i += TPB) {
        int k = i >> 4, c = i & 15;
        int gate = c >> 2, jj = c & 3;
        int gcol = gate * Hc + jbase + jj;
        float v;
        if (k < 256)      v = pWx[(size_t)k * (4 * Hc) + gcol];
        else if (k < 512) v = pWh[(size_t)(k - 256) * (4 * Hc) + gcol];
        else              v = pWs[(size_t)(k - 512) * (4 * Hc) + gcol];
        sm[OFF_WA + c * 772 + k] = v;
    }
    for (int i = tid; i < 8 * 512; i += TPB) {
        int k = i >> 3, c = i & 7;
        int kk = c >> 2, jj = c & 3;
        int j = jbase + jj;
        float v;
        if (k < 256) v = pWrx[(size_t)kk * Ec * Hc + (size_t)k * Hc + j];
        else         v = pWrh[(size_t)kk * Hc * Hc + (size_t)(k - 256) * Hc + j];
        sm[OFF_WB + c * 516 + k] = v;
    }
    if (tid < 16) {
        int gate = tid >> 2, jj = tid & 3;
        sm[OFF_BA + tid] = pB[gate * Hc + jbase + jj];
    }
    if (tid < 8) {
        int kk = tid >> 2, jj = tid & 3;
        sm[OFF_BB + tid] = pBr[kk * Hc + jbase + jj];
    }
    if (tid < 128) { sm[OFF_CLOC + tid] = 0.0f; sm[OFF_HTMP + tid] = 0.0f; }
    sm[OFF_SLOC + tid] = 0.0f;

    // prefetch x_0 / mask_0: per-warp self-sufficient mapping.
    {
        const int t0 = dir ? (Sc - 1) : 0;
        const float* xrow = inputs + ((size_t)lane * Sc + t0) * Ec + w32;
        #pragma unroll
        for (int j = 0; j < 8; ++j)
            cp16(&sm[OFF_SIN + lane * 772 + w32 + j * 4], xrow + j * 4);
        cp4(&sm[OFF_MASKW + warp * 32 + lane], mask + (size_t)lane * Sc + t0);
        CP_COMMIT;
    }
    __syncthreads();

    // acc2: z partials. Carries h-part across step boundary (zero at step 0).
    unsigned long long acc2[16];
    #pragma unroll
    for (int c = 0; c < 16; ++c) acc2[c] = 0ULL;
    unsigned long long accB[8];
    ulonglong2 hreg[8];
    unsigned cached_min = 0;   // warp0's cached min of same-dir flags

    for (int n = 0; n < Sc; ++n) {
        const int t = dir ? (Sc - 1 - n) : n;
        const int wpar = n & (NPAR - 1);              // write parity (h_n, s_n)
        const int rpar = (n + NPAR - 1) & (NPAR - 1); // read parity (s_{n-1})

        // ===== A: wait own x; wait s producers; z = x+s+h parts =====
        CP_WAIT0;
        wait_producers(dir, warp, lane, 2u * n);      // s_{n-1} visible
        {
            const float* ssrc = g_s + ((size_t)rpar * 2 + dir) * (Bc * Hc) + lane * 256 + w32;
            ulonglong2 sreg[8];
            #pragma unroll
            for (int j = 0; j < 8; ++j)
                sreg[j] = __ldcg(reinterpret_cast<const ulonglong2*>(ssrc + j * 4));
            accum_part<16, 772>(sm, acc2, OFF_SIN + lane * 772 + w32, OFF_WA + w32);
            accum_reg<16, 772>(sm, acc2, sreg, OFF_WA + 512 + w32);
        }
        #pragma unroll
        for (int c = 0; c < 16; ++c)
            sm[OFF_PRED + warp * 520 + c * 32 + lane] = pair_sum(acc2[c]);
        __syncthreads();

        // ===== A2: fused reduce + gates + mask blend =====
        if (tid < 128) {
            const int jj = tid >> 5, b = tid & 31;
            float zi = sm[OFF_BA + jj];
            float zf = sm[OFF_BA + 4 + jj];
            float zg = sm[OFF_BA + 8 + jj];
            float zo = sm[OFF_BA + 12 + jj];
            #pragma unroll
            for (int w = 0; w < 8; ++w) {
                const float* p = &sm[OFF_PRED + w * 520 + b];
                zi += p[(jj     ) * 32];
                zf += p[(jj +  4) * 32];
                zg += p[(jj +  8) * 32];
                zo += p[(jj + 12) * 32];
            }
            const float cold = sm[OFF_CLOC + tid];
            const float hold = sm[OFF_HTMP + tid];
            const float m    = sm[OFF_MASKW + (tid >> 5) * 32 + b];
            const float cn = sigf(zf) * cold + sigf(zi) * tanhf_fast(zg);
            const float hn = sigf(zo) * tanhf_fast(cn);
            const float h = m * hn + (1.0f - m) * hold;
            const float c = m * cn + (1.0f - m) * cold;
            sm[OFF_CLOC + tid] = c;
            sm[OFF_HTMP + tid] = h;
        }
        __syncthreads();

        // ===== A3: warp0: anti-dep bound, publish h FIRST, flag, then outputs =====
        if (tid < 32) {
            int need = 2 * n - (2 * NPAR - 3);
            if (need > 0) {
                while ((int)cached_min < need) {
                    unsigned m = 0xffffffffu;
                    #pragma unroll
                    for (int q = 0; q < 2; ++q) {
                        unsigned vv;
                        const unsigned* fp = &g_flags[(unsigned)(dir * 64 + lane * 2 + q) * 8];
                        asm volatile("ld.relaxed.gpu.u32 %0, [%1];" : "=r"(vv) : "l"(fp) : "memory");
                        if (vv < m) m = vv;
                    }
                    cached_min = __reduce_min_sync(0xffffffffu, m);
                    if ((int)cached_min < need) __nanosleep(32);
                }
            }
            const int b = tid;
            float4 hv = make_float4(sm[OFF_HTMP + b],      sm[OFF_HTMP + 32 + b],
                                    sm[OFF_HTMP + 64 + b], sm[OFF_HTMP + 96 + b]);
            float* hp = g_h + ((size_t)wpar * 2 + dir) * (Bc * Hc) + b * 256 + jbase;
            *reinterpret_cast<float4*>(hp) = hv;
            __syncwarp();
            if (lane == 0) flag_release(cta, 2u * n + 1u);
            // outputs after the release (not on the consumer-visible path)
            float4 cv = make_float4(sm[OFF_CLOC + b],      sm[OFF_CLOC + 32 + b],
                                    sm[OFF_CLOC + 64 + b], sm[OFF_CLOC + 96 + b]);
            size_t ob = (size_t)t * (Bc * 512) + (size_t)b * 512 + dir * 256 + jbase;
            *reinterpret_cast<float4*>(out + ob) = hv;
            *reinterpret_cast<float4*>(out + OUT_C + ob) = cv;
        }

        // ===== B0: r x-part (x_n still resident, own-lane rows) =====
        #pragma unroll
        for (int c = 0; c < 8; ++c) accB[c] = 0ULL;
        accum_part<8, 516>(sm, accB, OFF_SIN + lane * 772 + w32, OFF_WB + w32);

        // ===== B1: wait h producers; r h-part from registers =====
        wait_producers(dir, warp, lane, 2u * n + 1u);
        {
            const float* hsrc = g_h + ((size_t)wpar * 2 + dir) * (Bc * Hc) + lane * 256 + w32;
            #pragma unroll
            for (int j = 0; j < 8; ++j)
                hreg[j] = __ldcg(reinterpret_cast<const ulonglong2*>(hsrc + j * 4));
        }
        accum_reg<8, 516>(sm, accB, hreg, OFF_WB + 256 + w32);
        #pragma unroll
        for (int c = 0; c < 8; ++c)
            sm[OFF_PRED + warp * 520 + c * 32 + lane] = pair_sum(accB[c]);
        __syncthreads();

        // ===== B2: fused reduce + s update (256 threads) =====
        {
            const int o = tid;
            const int c = o >> 5, b = o & 31;
            const int jj = c & 3;
            float z = sm[OFF_BB + c];
            #pragma unroll
            for (int w = 0; w < 8; ++w) z += sm[OFF_PRED + w * 520 + o];
            const float r    = sigf(z);
            const float sold = sm[OFF_SLOC + o];
            const float cc   = sm[OFF_CLOC + jj * 32 + b];
            const float m    = sm[OFF_MASKW + (tid >> 5) * 32 + b];
            const float sn   = r * sold + (1.0f - r) * cc;
            sm[OFF_SLOC + o] = m * sn + (1.0f - m) * sold;
        }
        __syncthreads();

        // ===== B3: publish s[idx] FIRST, flag, then s outputs; prefetch x =====
        if (tid < 32) {
            const int b = tid;
            const int ibase = (idxv * 4) * 32 + b;
            float4 siv = make_float4(sm[OFF_SLOC + ibase],      sm[OFF_SLOC + ibase + 32],
                                     sm[OFF_SLOC + ibase + 64], sm[OFF_SLOC + ibase + 96]);
            *reinterpret_cast<float4*>(
                g_s + ((size_t)wpar * 2 + dir) * (Bc * Hc) + b * 256 + jbase) = siv;
            __syncwarp();
            if (lane == 0) flag_release(cta, 2u * n + 2u);
            #pragma unroll
            for (int kk = 0; kk < 2; ++kk) {
                const int base = (kk * 4) * 32 + b;
                float4 sv = make_float4(sm[OFF_SLOC + base],      sm[OFF_SLOC + base + 32],
                                        sm[OFF_SLOC + base + 64], sm[OFF_SLOC + base + 96]);
                size_t ob = (size_t)kk * ((size_t)Sc * Bc * 512)
                          + (size_t)t * (Bc * 512) + (size_t)b * 512 + dir * 256 + jbase;
                *reinterpret_cast<float4*>(out + OUT_S + ob) = sv;
            }
        }
        if (n + 1 < Sc) {
            const int tn = dir ? (Sc - 2 - n) : (n + 1);
            const float* xrow = inputs + ((size_t)lane * Sc + tn) * Ec + w32;
            #pragma unroll
            for (int j = 0; j < 8; ++j)
                cp16(&sm[OFF_SIN + lane * 772 + w32 + j * 4], xrow + j * 4);
            cp4(&sm[OFF_MASKW + warp * 32 + lane], mask + (size_t)lane * Sc + tn);
        }
        CP_COMMIT;

        // ===== B4: z h-part for step n+1 (from hreg, no loads, no sync) =====
        #pragma unroll
        for (int c = 0; c < 16; ++c) acc2[c] = 0ULL;
        accum_reg<16, 772>(sm, acc2, hreg, OFF_WA + 256 + w32);
    }
}

extern "C" void kernel_launch(void* const* d_in, const int* in_sizes, int n_in,
                              void* d_out, int out_size) {
    (void)in_sizes; (void)n_in; (void)out_size;
    cudaFuncSetAttribute(bislstm_kernel,
                         cudaFuncAttributeMaxDynamicSharedMemorySize, SMEM_BYTES);
    init_kernel<<<64, 256>>>();
    bislstm_kernel<<<NCTA, TPB, SMEM_BYTES>>>(
        (const float*)d_in[0],  (const float*)d_in[1],
        (const float*)d_in[2],  (const float*)d_in[3],
        (const float*)d_in[4],  (const float*)d_in[5],
        (const float*)d_in[6],  (const float*)d_in[7],
        (const float*)d_in[8],
        (const float*)d_in[9],  (const float*)d_in[10],
        (const float*)d_in[11], (const float*)d_in[12],
        (const float*)d_in[13], (const float*)d_in[14],
        (const float*)d_in[15],
        (const int*)d_in[16],   (float*)d_out);
}